// round 8
// baseline (speedup 1.0000x reference)
#include <cuda_runtime.h>

#define BATCH 64
#define NJ 21
#define BJ (BATCH * NJ)        // 1344
#define IMG 256

// w[d] = exp(-d^2 / (2 * 2.5^2)) = exp(-d^2 / 12.5), d = 0..5
__constant__ float c_w[6] = {
    1.0f,
    0.92311634638663580f,   // exp(-0.08)
    0.72614903707369090f,   // exp(-0.32)
    0.48675225595997170f,   // exp(-0.72)
    0.27803730045319410f,   // exp(-1.28)
    0.13533528323661270f    // exp(-2.00)
};

// Patch kernel: one block per (batch, joint) map. Thread 0 computes the
// fisheye seed in double (matches jnp round-half-to-even; avoids trig via
// cos(phi)=x/rho, sin(phi)=y/rho). Threads 0..120 then stamp the 11x11
// gaussian patch (clipped to the image) on top of the memset-zeroed output.
__global__ void __launch_bounds__(128) patch_kernel(float* __restrict__ out,
                                                    const float* __restrict__ joint) {
    __shared__ int2 s_seed;

    const unsigned bj = blockIdx.x;

    if (threadIdx.x == 0) {
        double x = (double)joint[bj * 3 + 0];
        double y = (double)joint[bj * 3 + 1];
        double z = (double)joint[bj * 3 + 2];
        double rho = sqrt(x * x + y * y);
        double theta = atan2(rho, z);
        double r = 128.0 * theta / 1.5707963267948966;  // RADIUS * theta / (pi/2)
        double cphi, sphi;
        if (rho > 0.0) { cphi = x / rho; sphi = y / rho; }
        else           { cphi = 1.0;     sphi = 0.0;     }
        int sx = (int)rint(128.0 + r * cphi);
        int sy = (int)rint(128.0 + r * sphi);
        sx = min(max(sx, 0), IMG - 1);
        sy = min(max(sy, 0), IMG - 1);
        s_seed = make_int2(sx, sy);
    }
    __syncthreads();

    const unsigned t = threadIdx.x;
    if (t >= 121) return;

    const int2 s = s_seed;
    const int dy = (int)(t / 11) - 5;   // -5..5
    const int dx = (int)(t % 11) - 5;   // -5..5
    const int y  = s.y + dy;
    const int x  = s.x + dx;
    if ((unsigned)y < IMG && (unsigned)x < IMG) {
        const int ady = dy < 0 ? -dy : dy;
        const int adx = dx < 0 ? -dx : dx;
        out[(size_t)bj * (IMG * IMG) + (size_t)y * IMG + x] = c_w[ady] * c_w[adx];
    }
}

extern "C" void kernel_launch(void* const* d_in, const int* in_sizes, int n_in,
                              void* d_out, int out_size) {
    const float* joint = (const float*)d_in[0];

    // 1) zero-fill the whole output via the driver's fill path (graph memset
    //    node — capturable, allocation-free). 99.54% of the output is zero.
    cudaMemsetAsync(d_out, 0, (size_t)BJ * IMG * IMG * sizeof(float));

    // 2) stamp the 1344 gaussian 11x11 patches (~650 KB of writes).
    patch_kernel<<<BJ, 128>>>((float*)d_out, joint);
}

// round 9
// speedup vs baseline: 1.0222x; 1.0222x over previous
#include <cuda_runtime.h>

#define BATCH 64
#define NJ 21
#define BJ (BATCH * NJ)        // 1344
#define IMG 256

__device__ int2 g_seeds[BJ];

// w[d] = exp(-d^2 / (2 * 2.5^2)) = exp(-d^2 / 12.5), d = 0..5
__constant__ float c_w[6] = {
    1.0f,
    0.92311634638663580f,   // exp(-0.08)
    0.72614903707369090f,   // exp(-0.32)
    0.48675225595997170f,   // exp(-0.72)
    0.27803730045319410f,   // exp(-1.28)
    0.13533528323661270f    // exp(-2.00)
};

// 1344 parallel fisheye projections, one thread each, 32-thread blocks spread
// over 42 SMs so the (slow) FP64 pipe is not a serial bottleneck.
// Double precision matches jnp round-half-to-even exactly; avoids trig via
// cos(phi)=x/rho, sin(phi)=y/rho.
__global__ void __launch_bounds__(32) seed_kernel(const float* __restrict__ joint) {
    int i = blockIdx.x * 32 + threadIdx.x;
    if (i >= BJ) return;
    double x = (double)joint[i * 3 + 0];
    double y = (double)joint[i * 3 + 1];
    double z = (double)joint[i * 3 + 2];
    double rho = sqrt(x * x + y * y);
    double theta = atan2(rho, z);
    double r = 128.0 * theta / 1.5707963267948966;  // RADIUS * theta / (pi/2)
    double cphi, sphi;
    if (rho > 0.0) { cphi = x / rho; sphi = y / rho; }
    else           { cphi = 1.0;     sphi = 0.0;     }
    int sx = (int)rint(128.0 + r * cphi);
    int sy = (int)rint(128.0 + r * sphi);
    sx = min(max(sx, 0), IMG - 1);
    sy = min(max(sy, 0), IMG - 1);
    g_seeds[i] = make_int2(sx, sy);
}

// Stamp the 11x11 gaussian patch for each map on top of the zeroed output.
// No FP64, no barrier: every thread reads its block's seed (broadcast) and
// writes at most one pixel.
__global__ void __launch_bounds__(128) patch_kernel(float* __restrict__ out) {
    const unsigned bj = blockIdx.x;
    const unsigned t  = threadIdx.x;
    if (t >= 121) return;

    const int2 s = g_seeds[bj];
    const int dy = (int)(t / 11) - 5;   // -5..5
    const int dx = (int)(t % 11) - 5;   // -5..5
    const int y  = s.y + dy;
    const int x  = s.x + dx;
    if ((unsigned)y < IMG && (unsigned)x < IMG) {
        const int ady = dy < 0 ? -dy : dy;
        const int adx = dx < 0 ? -dx : dx;
        out[(size_t)bj * (IMG * IMG) + (size_t)y * IMG + x] = c_w[ady] * c_w[adx];
    }
}

extern "C" void kernel_launch(void* const* d_in, const int* in_sizes, int n_in,
                              void* d_out, int out_size) {
    const float* joint = (const float*)d_in[0];

    // 1) project all 1344 joints in parallel (no dependence on d_out)
    seed_kernel<<<(BJ + 31) / 32, 32>>>(joint);

    // 2) zero-fill the output via the driver's fill path (~7.3 TB/s measured,
    //    faster than any SM store kernel we've built). Graph memset node.
    cudaMemsetAsync(d_out, 0, (size_t)BJ * IMG * IMG * sizeof(float));

    // 3) stamp the 1344 gaussian 11x11 patches (~650 KB of writes).
    patch_kernel<<<BJ, 128>>>((float*)d_out);
}